// round 11
// baseline (speedup 1.0000x reference)
#include <cuda_runtime.h>
#include <cuda_fp16.h>
#include <cstdint>

// Problem constants
// u_t    [16,3,32,32]  f32   d_in[0]
// h_prev [16,9,128,64,64] f32 d_in[1]
// action [16,2] int32         d_in[2]
// W_u    [128,3,3,3] f32      d_in[3]
// W_h    [128,128,3,3] f32    d_in[4]
// out    [16,9,128,64,64] f32
#define WORLD 64
#define WIN   32
#define CC    128
#define VV    9

// ---- smem layout (per CTA, dynamic) ----
// P planes (x2): u64[16 slices][276]  (slice = ks*4+kq; row rc = ry*68+xx, ry 0..3, xx 0..65)
//   u64 = (half2 at ci-pair p = 8ks+kq, half2 at p+4); half2 = (ci=2p, ci=2p+1)
// W planes (x2): u64[16 slices][132]  (idx = co)
#define PD_BYTES (16*276*8)              // 35328
#define WD_BYTES (16*132*8)              // 16896
#define SM_W     (2*PD_BYTES)            // 70656
#define SMEM_TOTAL (2*PD_BYTES + 2*WD_BYTES)   // 104448  (x2 CTAs = 204KB/SM)

// Scratch (device globals; no allocation allowed)
__device__ __align__(16) uint32_t g_W32[18 * 4224];          // [plane=chunk*9+tap] smem W images
__device__ __align__(16) uint32_t g_h16[144 * 64 * 64 * 64]; // [bv][ci-pair][y][x] half2
__device__ float g_uconv[16 * 128 * 32 * 32];                // [b][co][y][x]

// ---------------- helpers ----------------
__device__ __forceinline__ uint32_t smem_u32(const void* p) {
    uint32_t a;
    asm("{ .reg .u64 t; cvta.to.shared.u64 t, %1; cvt.u32.u64 %0, t; }" : "=r"(a) : "l"(p));
    return a;
}
__device__ __forceinline__ void lds64(uint32_t& lo, uint32_t& hi, uint32_t addr) {
    asm volatile("ld.shared.v2.b32 {%0,%1}, [%2];" : "=r"(lo), "=r"(hi) : "r"(addr));
}
__device__ __forceinline__ void mma_f16(float c[4], const uint32_t a[4], const uint32_t b[2]) {
    asm volatile(
        "mma.sync.aligned.m16n8k16.row.col.f32.f16.f16.f32 "
        "{%0,%1,%2,%3}, {%4,%5,%6,%7}, {%8,%9}, {%0,%1,%2,%3};"
        : "+f"(c[0]), "+f"(c[1]), "+f"(c[2]), "+f"(c[3])
        : "r"(a[0]), "r"(a[1]), "r"(a[2]), "r"(a[3]), "r"(b[0]), "r"(b[1]));
}
__device__ __forceinline__ void cpa4(uint32_t dst, const void* src) {
    asm volatile("cp.async.ca.shared.global [%0], [%1], 4;" :: "r"(dst), "l"(src));
}
__device__ __forceinline__ void cpa_commit() {
    asm volatile("cp.async.commit_group;" ::: "memory");
}
__device__ __forceinline__ void cpa_wait0() {
    asm volatile("cp.async.wait_group 0;" ::: "memory");
}

// ---------- prep: W_h -> fp16 weight planes (smem W images) ----------
__global__ void prep_w_kernel(const float* __restrict__ W_h) {
    int idx = blockIdx.x * blockDim.x + threadIdx.x;
    if (idx >= 18 * 16 * 128 * 2) return;
    int co    = idx & 127;
    int hi    = (idx >> 7) & 1;
    int s     = (idx >> 8) & 15;
    int plane = idx >> 12;            // 0..17 = chunk*9+tap
    int tap   = plane % 9;
    int chunk = plane / 9;
    int ks = s >> 2, kq = s & 3;
    int ci = chunk * 64 + ks * 16 + 2 * kq + hi * 8;
    float v0 = W_h[((size_t)co * 128 + ci) * 9 + tap];
    float v1 = W_h[((size_t)co * 128 + ci + 1) * 9 + tap];
    __half2 h = __floats2half2_rn(v0, v1);
    g_W32[(size_t)plane * 4224 + ((s * 132 + co) * 2 + hi)] = *(uint32_t*)&h;
}

// ---------- prep: h_prev -> half2 ci-pair planes (velocity channel-roll NOT baked; per-v roll is) ----------
// g_h16[bv][P 0..63][y][x] = half2( h[b,v, 2P, y, x], h[b,v, 2P+1, y, x] )
// (the (ci - vy) roll depends on v only through ci index; baked in main via pair-granular access:
//  main reads pair index with the channel roll applied at pair resolution — vy in {-1,0,1} shifts ci
//  by +-1 which crosses pair boundaries, so we bake the roll HERE per (b,v).)
__global__ void prep_h_kernel(const float* __restrict__ h_prev) {
    size_t idx = (size_t)blockIdx.x * 256 + threadIdx.x;
    if (idx >= (size_t)144 * 64 * 64 * 64) return;
    int xx = idx & 63;
    int gy = (idx >> 6) & 63;
    int p  = (idx >> 12) & 63;
    int bv = idx >> 18;                 // b*9+v
    int v  = bv % 9;
    int vy = v % 3 - 1;
    int c0 = (2 * p - vy + 128) & 127;
    int c1 = (2 * p + 1 - vy + 128) & 127;
    const float* hp = h_prev + (size_t)bv * CC * 4096;
    float f0 = hp[(size_t)c0 * 4096 + gy * 64 + xx];
    float f1 = hp[(size_t)c1 * 4096 + gy * 64 + xx];
    __half2 h = __floats2half2_rn(f0, f1);
    g_h16[idx] = *(uint32_t*)&h;
}

// ---------- encoder: circular conv u_t * W_u -> g_uconv (exact f32) ----------
__global__ void encoder_kernel(const float* __restrict__ u_t,
                               const float* __restrict__ W_u) {
    int co = blockIdx.x;
    int b  = blockIdx.y;
    __shared__ float us[3 * 32 * 32];
    __shared__ float ws[27];
    int tid = threadIdx.x;
    const float* up = u_t + (size_t)b * 3 * 1024;
    for (int e = tid; e < 3072; e += 256) us[e] = up[e];
    if (tid < 27) ws[tid] = W_u[co * 27 + tid];
    __syncthreads();

    int y  = (tid * 4) >> 5;
    int x0 = (tid * 4) & 31;
    float acc[4] = {0.f, 0.f, 0.f, 0.f};
#pragma unroll
    for (int ci = 0; ci < 3; ++ci)
#pragma unroll
        for (int ky = 0; ky < 3; ++ky) {
            int yy = (y + ky - 1 + 32) & 31;
#pragma unroll
            for (int kx = 0; kx < 3; ++kx) {
                float w = ws[ci * 9 + ky * 3 + kx];
#pragma unroll
                for (int k = 0; k < 4; ++k) {
                    int xx = (x0 + k + kx - 1 + 32) & 31;
                    acc[k] = fmaf(w, us[ci * 1024 + yy * 32 + xx], acc[k]);
                }
            }
        }
    float4 r = {acc[0], acc[1], acc[2], acc[3]};
    *(float4*)&g_uconv[((size_t)(b * 128 + co) * 32 + y) * 32 + x0] = r;
}

// ---------- main: fp16 m16n8k16, cp.async P builds double-buffered across chunks ----------
// Block = (2-row tile, v, b); D[co=128][px=128]; 8 warps: wco=wid&1, wpx=wid>>1; 2 CTAs/SM.
__global__ __launch_bounds__(256, 2)
void fernn_f16_kernel(const int* __restrict__ action,
                      float* __restrict__ out) {
    extern __shared__ unsigned char smem[];
    uint32_t sb = smem_u32(smem);

    int tid  = threadIdx.x;
    int wid  = tid >> 5;
    int lane = tid & 31;
    int wco = wid & 1;            // co half (64)
    int wpx = wid >> 1;           // 0..3
    int rl  = wpx >> 1;           // output row in tile (0..1)
    int xh  = wpx & 1;            // x half (32 px)
    int kq  = lane & 3;
    int lq  = lane >> 2;          // 0..7

    int y0 = blockIdx.x * 2;
    int v  = blockIdx.y;
    int b  = blockIdx.z;

    int ax = action[b * 2 + 0];
    int ay = action[b * 2 + 1];
    int vx = v / 3 - 1;
    // folded index (verified R2): in = h_prev[b,v,(ci-vy)%C,(y+ky-1+Sy)%H,(x+kx-1+Sx)%W]
    // channel roll baked into g_h16; here only spatial shifts:
    int Sy = ay - vx;
    int Sx = ax;
    const uint32_t* hbase = g_h16 + (size_t)(b * VV + v) * 64 * 4096;

    // ---- P-build thread mapping: row = tid>>1 (p 0..31, ry 0..3), half = tid&1 (33 cols) ----
    int prow = tid >> 1;
    int pb_p  = prow >> 2;        // within-chunk ci-pair 0..31
    int pb_ry = prow & 3;
    int pb_hf = tid & 1;
    int pks = pb_p >> 3, prem = pb_p & 7;
    int pkq = prem & 3, phi = prem >> 2;
    uint32_t pdst0 = (uint32_t)((((pks * 4 + pkq) * 276 + pb_ry * 68) * 2 + phi) * 4)
                   + (uint32_t)(pb_hf * 33 * 8);
    int pgy = (y0 - 1 + pb_ry + Sy + 128) & 63;
    int pgx0 = pb_hf * 33 - 1 + Sx + 64;   // add j, then &63

    // build P for 'chunk' into buffer (chunk&1)
    auto issueP = [&](int chunk) {
        const uint32_t* src = hbase + (size_t)(chunk * 32 + pb_p) * 4096 + pgy * 64;
        uint32_t dst = sb + (uint32_t)((chunk & 1) * PD_BYTES) + pdst0;
#pragma unroll
        for (int j = 0; j < 33; ++j)
            cpa4(dst + j * 8, src + ((pgx0 + j) & 63));
    };

    float acc[4][4][4];
#pragma unroll
    for (int mt = 0; mt < 4; ++mt)
#pragma unroll
        for (int nt = 0; nt < 4; ++nt)
#pragma unroll
            for (int c = 0; c < 4; ++c) acc[mt][nt][c] = 0.f;

    // ---- prologue: P0 async + W0 sync ----
    issueP(0);
    cpa_commit();
    {
        const float4* wsrc = (const float4*)g_W32;
        float4* wdst = (float4*)(smem + SM_W);
        for (int i = tid; i < 1056; i += 256) wdst[i] = wsrc[i];
    }
    cpa_wait0();
    __syncthreads();

#pragma unroll 1
    for (int chunk = 0; chunk < 2; ++chunk) {
        if (chunk == 0) {
            issueP(1);       // overlaps with chunk-0 MMAs
            cpa_commit();
        }

#pragma unroll 1
        for (int t = 0; t < 9; ++t) {
            int s  = chunk * 9 + t;
            int dy = t / 3;
            int dx = t % 3;

            // prefetch next W plane into alternate buffer (overlaps with MMAs)
            if (s < 17) {
                const float4* wsrc = (const float4*)(g_W32 + (size_t)(s + 1) * 4224);
                float4* wdst = (float4*)(smem + SM_W + (size_t)((s + 1) & 1) * WD_BYTES);
                for (int i = tid; i < 1056; i += 256) wdst[i] = wsrc[i];
            }

            uint32_t wbase = sb + SM_W + (uint32_t)((s & 1) * WD_BYTES);
            uint32_t pbuf  = sb + (uint32_t)((chunk & 1) * PD_BYTES);
            // B row base: slice sl=ks*4+kq, row (rl+dy), column (px + dx), px = xh*32+nt*8+lq
            uint32_t bb = pbuf + (uint32_t)(((rl + dy) * 68 + xh * 32 + lq + dx) * 8);

#pragma unroll
            for (int ks = 0; ks < 4; ++ks) {
                int sl = ks * 4 + kq;
                uint32_t A[4][4];
                uint32_t ab = wbase + (uint32_t)((sl * 132) * 8);
#pragma unroll
                for (int mt = 0; mt < 4; ++mt) {
                    int co = wco * 64 + mt * 16 + lq;
                    lds64(A[mt][0], A[mt][2], ab + co * 8);
                    lds64(A[mt][1], A[mt][3], ab + (co + 8) * 8);
                }
                uint32_t bbs = bb + (uint32_t)((sl * 276) * 8);
#pragma unroll
                for (int nt = 0; nt < 4; ++nt) {
                    uint32_t B[2];
                    lds64(B[0], B[1], bbs + nt * 64);
#pragma unroll
                    for (int mt = 0; mt < 4; ++mt) mma_f16(acc[mt][nt], A[mt], B);
                }
            }
            __syncthreads();
        }
        if (chunk == 0) {
            cpa_wait0();     // P1 resident
            __syncthreads();
        }
    }

    // ---- epilogue: +u (top-left window), relu, store ----
    int y = y0 + rl;
    float* obase = out + (size_t)((b * VV + v) * CC) * 4096 + (size_t)y * 64;
    bool rowu = (y < WIN);

#pragma unroll
    for (int mt = 0; mt < 4; ++mt) {
        int co = wco * 64 + mt * 16 + lq;
#pragma unroll
        for (int nt = 0; nt < 4; ++nt) {
            int px = xh * 32 + nt * 8 + 2 * kq;
            float2 v0 = {acc[mt][nt][0], acc[mt][nt][1]};
            float2 v1 = {acc[mt][nt][2], acc[mt][nt][3]};
            if (rowu && px < WIN) {
                const float* u0 = g_uconv + (size_t)(b * CC + co) * 1024 + y * 32 + px;
                const float* u1 = g_uconv + (size_t)(b * CC + co + 8) * 1024 + y * 32 + px;
                v0.x += u0[0]; v0.y += u0[1];
                v1.x += u1[0]; v1.y += u1[1];
            }
            v0.x = fmaxf(v0.x, 0.f); v0.y = fmaxf(v0.y, 0.f);
            v1.x = fmaxf(v1.x, 0.f); v1.y = fmaxf(v1.y, 0.f);
            *(float2*)(obase + (size_t)co * 4096 + px)       = v0;
            *(float2*)(obase + (size_t)(co + 8) * 4096 + px) = v1;
        }
    }
}

extern "C" void kernel_launch(void* const* d_in, const int* in_sizes, int n_in,
                              void* d_out, int out_size) {
    const float* u_t    = (const float*)d_in[0];
    const float* h_prev = (const float*)d_in[1];
    const int*   action = (const int*)d_in[2];
    const float* W_u    = (const float*)d_in[3];
    const float* W_h    = (const float*)d_in[4];
    float* out = (float*)d_out;

    cudaFuncSetAttribute(fernn_f16_kernel,
                         cudaFuncAttributeMaxDynamicSharedMemorySize, SMEM_TOTAL);

    prep_w_kernel<<<(18 * 16 * 128 * 2 + 255) / 256, 256>>>(W_h);
    prep_h_kernel<<<(int)(((size_t)144 * 64 * 64 * 64 + 255) / 256), 256>>>(h_prev);
    encoder_kernel<<<dim3(128, 16), 256>>>(u_t, W_u);
    fernn_f16_kernel<<<dim3(32, 9, 16), 256, SMEM_TOTAL>>>(action, out);
}

// round 13
// speedup vs baseline: 1.0917x; 1.0917x over previous
#include <cuda_runtime.h>
#include <cuda_fp16.h>
#include <cstdint>

// Problem constants
// u_t    [16,3,32,32]  f32   d_in[0]
// h_prev [16,9,128,64,64] f32 d_in[1]
// action [16,2] int32         d_in[2]
// W_u    [128,3,3,3] f32      d_in[3]
// W_h    [128,128,3,3] f32    d_in[4]
// out    [16,9,128,64,64] f32
#define WORLD 64
#define WIN   32
#define CC    128
#define VV    9

// ---- smem layout (per CTA, dynamic): two P planes only ----
// P plane: u64[16 slices][276]  (slice = ks*4+kq; row rc = ry*68+xx, ry 0..3, xx 0..65)
//   u64 = (half2 at ci-pair p = 8ks+kq, half2 at p+4); half2 = (ci=2p, ci=2p+1)
#define PD_BYTES (16*276*8)              // 35328
#define SMEM_TOTAL (2*PD_BYTES)          // 70656  (x2 CTAs = 138KB/SM)

// Scratch (device globals; no allocation allowed)
// g_Wg: [plane 18][sl 16][ct 8][lq 8] uint4 — per-thread A fragments (one LDG.128 each)
__device__ __align__(16) uint4 g_Wg[18 * 16 * 8 * 8];
__device__ __align__(16) uint32_t g_h16[144 * 64 * 64 * 64]; // [bv][ci-pair][y][x] half2
__device__ float g_uconv[16 * 128 * 32 * 32];                // [b][co][y][x]

// ---------------- helpers ----------------
__device__ __forceinline__ uint32_t smem_u32(const void* p) {
    uint32_t a;
    asm("{ .reg .u64 t; cvta.to.shared.u64 t, %1; cvt.u32.u64 %0, t; }" : "=r"(a) : "l"(p));
    return a;
}
__device__ __forceinline__ void lds64(uint32_t& lo, uint32_t& hi, uint32_t addr) {
    asm volatile("ld.shared.v2.b32 {%0,%1}, [%2];" : "=r"(lo), "=r"(hi) : "r"(addr));
}
__device__ __forceinline__ void mma_f16(float c[4], const uint4 a, const uint32_t b0, const uint32_t b1) {
    asm volatile(
        "mma.sync.aligned.m16n8k16.row.col.f32.f16.f16.f32 "
        "{%0,%1,%2,%3}, {%4,%5,%6,%7}, {%8,%9}, {%0,%1,%2,%3};"
        : "+f"(c[0]), "+f"(c[1]), "+f"(c[2]), "+f"(c[3])
        : "r"(a.x), "r"(a.y), "r"(a.z), "r"(a.w), "r"(b0), "r"(b1));
}
__device__ __forceinline__ void cpa4(uint32_t dst, const void* src) {
    asm volatile("cp.async.ca.shared.global [%0], [%1], 4;" :: "r"(dst), "l"(src));
}
__device__ __forceinline__ void cpa_commit() {
    asm volatile("cp.async.commit_group;" ::: "memory");
}
__device__ __forceinline__ void cpa_wait0() {
    asm volatile("cp.async.wait_group 0;" ::: "memory");
}

// ---------- prep: W_h -> per-thread fp16 A-fragment image ----------
// component idx = (((plane*16+sl)*8+ct)*8+lq)*4 + c
// c: co += (c&1)*8 ; ci += (c>>1)*8
__global__ void prep_w_kernel(const float* __restrict__ W_h) {
    int idx = blockIdx.x * blockDim.x + threadIdx.x;
    if (idx >= 18 * 16 * 8 * 8 * 4) return;
    int c     = idx & 3;
    int lq    = (idx >> 2) & 7;
    int ct    = (idx >> 5) & 7;
    int sl    = (idx >> 8) & 15;
    int plane = idx >> 12;            // 0..17 = chunk*9+tap
    int tap   = plane % 9;
    int chunk = plane / 9;
    int ks = sl >> 2, kq = sl & 3;
    int co = ct * 16 + lq + (c & 1) * 8;
    int ci = chunk * 64 + ks * 16 + 2 * kq + (c >> 1) * 8;
    float v0 = W_h[((size_t)co * 128 + ci) * 9 + tap];
    float v1 = W_h[((size_t)co * 128 + ci + 1) * 9 + tap];
    __half2 h = __floats2half2_rn(v0, v1);
    ((uint32_t*)g_Wg)[idx] = *(uint32_t*)&h;
}

// ---------- prep: h_prev -> half2 ci-pair planes (channel roll baked per (b,v)) ----------
__global__ void prep_h_kernel(const float* __restrict__ h_prev) {
    size_t idx = (size_t)blockIdx.x * 256 + threadIdx.x;
    if (idx >= (size_t)144 * 64 * 64 * 64) return;
    int xx = idx & 63;
    int gy = (idx >> 6) & 63;
    int p  = (idx >> 12) & 63;
    int bv = idx >> 18;                 // b*9+v
    int v  = bv % 9;
    int vy = v % 3 - 1;
    int c0 = (2 * p - vy + 128) & 127;
    int c1 = (2 * p + 1 - vy + 128) & 127;
    const float* hp = h_prev + (size_t)bv * CC * 4096;
    float f0 = hp[(size_t)c0 * 4096 + gy * 64 + xx];
    float f1 = hp[(size_t)c1 * 4096 + gy * 64 + xx];
    __half2 h = __floats2half2_rn(f0, f1);
    g_h16[idx] = *(uint32_t*)&h;
}

// ---------- encoder: circular conv u_t * W_u -> g_uconv (exact f32) ----------
__global__ void encoder_kernel(const float* __restrict__ u_t,
                               const float* __restrict__ W_u) {
    int co = blockIdx.x;
    int b  = blockIdx.y;
    __shared__ float us[3 * 32 * 32];
    __shared__ float ws[27];
    int tid = threadIdx.x;
    const float* up = u_t + (size_t)b * 3 * 1024;
    for (int e = tid; e < 3072; e += 256) us[e] = up[e];
    if (tid < 27) ws[tid] = W_u[co * 27 + tid];
    __syncthreads();

    int y  = (tid * 4) >> 5;
    int x0 = (tid * 4) & 31;
    float acc[4] = {0.f, 0.f, 0.f, 0.f};
#pragma unroll
    for (int ci = 0; ci < 3; ++ci)
#pragma unroll
        for (int ky = 0; ky < 3; ++ky) {
            int yy = (y + ky - 1 + 32) & 31;
#pragma unroll
            for (int kx = 0; kx < 3; ++kx) {
                float w = ws[ci * 9 + ky * 3 + kx];
#pragma unroll
                for (int k = 0; k < 4; ++k) {
                    int xx = (x0 + k + kx - 1 + 32) & 31;
                    acc[k] = fmaf(w, us[ci * 1024 + yy * 32 + xx], acc[k]);
                }
            }
        }
    float4 r = {acc[0], acc[1], acc[2], acc[3]};
    *(float4*)&g_uconv[((size_t)(b * 128 + co) * 32 + y) * 32 + x0] = r;
}

// ---------- main: fp16 m16n8k16; A from global (L1-cached LDG.128); barrier-free taps ----------
// Block = (2-row tile, v, b); D[co=128][px=128]; 8 warps: wco=wid&1, wpx=wid>>1; 2 CTAs/SM.
__global__ __launch_bounds__(256, 2)
void fernn_f16_kernel(const int* __restrict__ action,
                      float* __restrict__ out) {
    extern __shared__ unsigned char smem[];
    uint32_t sb = smem_u32(smem);

    int tid  = threadIdx.x;
    int wid  = tid >> 5;
    int lane = tid & 31;
    int wco = wid & 1;            // co half (64)
    int wpx = wid >> 1;           // 0..3
    int rl  = wpx >> 1;           // output row in tile (0..1)
    int xh  = wpx & 1;            // x half (32 px)
    int kq  = lane & 3;
    int lq  = lane >> 2;          // 0..7

    int y0 = blockIdx.x * 2;
    int v  = blockIdx.y;
    int b  = blockIdx.z;

    int ax = action[b * 2 + 0];
    int ay = action[b * 2 + 1];
    int vx = v / 3 - 1;
    // folded index (verified R2): in = h_prev[b,v,(ci-vy)%C,(y+ky-1+Sy)%H,(x+kx-1+Sx)%W]
    // channel roll baked into g_h16; here only spatial shifts:
    int Sy = ay - vx;
    int Sx = ax;
    const uint32_t* hbase = g_h16 + (size_t)(b * VV + v) * 64 * 4096;

    // ---- P-build thread mapping: row = tid>>1 (p 0..31, ry 0..3), half = tid&1 (33 cols) ----
    int prow = tid >> 1;
    int pb_p  = prow >> 2;        // within-chunk ci-pair 0..31
    int pb_ry = prow & 3;
    int pb_hf = tid & 1;
    int pks = pb_p >> 3, prem = pb_p & 7;
    int pkq = prem & 3, phi = prem >> 2;
    uint32_t pdst0 = (uint32_t)((((pks * 4 + pkq) * 276 + pb_ry * 68) * 2 + phi) * 4)
                   + (uint32_t)(pb_hf * 33 * 8);
    int pgy = (y0 - 1 + pb_ry + Sy + 128) & 63;
    int pgx0 = pb_hf * 33 - 1 + Sx + 64;   // add j, then &63

    // build P for 'chunk' into buffer (chunk&1)
    auto issueP = [&](int chunk) {
        const uint32_t* src = hbase + (size_t)(chunk * 32 + pb_p) * 4096 + pgy * 64;
        uint32_t dst = sb + (uint32_t)((chunk & 1) * PD_BYTES) + pdst0;
#pragma unroll
        for (int j = 0; j < 33; ++j)
            cpa4(dst + j * 8, src + ((pgx0 + j) & 63));
    };

    float acc[4][4][4];
#pragma unroll
    for (int mt = 0; mt < 4; ++mt)
#pragma unroll
        for (int nt = 0; nt < 4; ++nt)
#pragma unroll
            for (int c = 0; c < 4; ++c) acc[mt][nt][c] = 0.f;

    // ---- prologue: P0 async; wait; then issue P1 (overlaps chunk-0 MMAs) ----
    issueP(0);
    cpa_commit();
    cpa_wait0();
    __syncthreads();
    issueP(1);
    cpa_commit();

#pragma unroll 1
    for (int chunk = 0; chunk < 2; ++chunk) {
        uint32_t pbuf = sb + (uint32_t)((chunk & 1) * PD_BYTES);

#pragma unroll 1
        for (int t = 0; t < 9; ++t) {
            int plane = chunk * 9 + t;
            int dy = t / 3;
            int dx = t % 3;
            // B row base: slice sl, row (rl+dy), column (px+dx), px = xh*32+nt*8+lq
            uint32_t bb = pbuf + (uint32_t)(((rl + dy) * 68 + xh * 32 + lq + dx) * 8);
            const uint4* wp = g_Wg + ((size_t)(plane * 16) * 8 + wco * 4) * 8 + lq;

#pragma unroll
            for (int ks = 0; ks < 4; ++ks) {
                int sl = ks * 4 + kq;
                uint4 A[4];
#pragma unroll
                for (int mt = 0; mt < 4; ++mt)
                    A[mt] = __ldg(wp + ((size_t)sl * 8 + mt) * 8);
                uint32_t bbs = bb + (uint32_t)((sl * 276) * 8);
#pragma unroll
                for (int nt = 0; nt < 4; ++nt) {
                    uint32_t B0, B1;
                    lds64(B0, B1, bbs + nt * 64);
#pragma unroll
                    for (int mt = 0; mt < 4; ++mt) mma_f16(acc[mt][nt], A[mt], B0, B1);
                }
            }
        }
        if (chunk == 0) {
            cpa_wait0();     // P1 resident
            __syncthreads();
        }
    }

    // ---- epilogue: +u (top-left window), relu, store ----
    int y = y0 + rl;
    float* obase = out + (size_t)((b * VV + v) * CC) * 4096 + (size_t)y * 64;
    bool rowu = (y < WIN);

#pragma unroll
    for (int mt = 0; mt < 4; ++mt) {
        int co = wco * 64 + mt * 16 + lq;
#pragma unroll
        for (int nt = 0; nt < 4; ++nt) {
            int px = xh * 32 + nt * 8 + 2 * kq;
            float2 v0 = {acc[mt][nt][0], acc[mt][nt][1]};
            float2 v1 = {acc[mt][nt][2], acc[mt][nt][3]};
            if (rowu && px < WIN) {
                const float* u0 = g_uconv + (size_t)(b * CC + co) * 1024 + y * 32 + px;
                const float* u1 = g_uconv + (size_t)(b * CC + co + 8) * 1024 + y * 32 + px;
                v0.x += u0[0]; v0.y += u0[1];
                v1.x += u1[0]; v1.y += u1[1];
            }
            v0.x = fmaxf(v0.x, 0.f); v0.y = fmaxf(v0.y, 0.f);
            v1.x = fmaxf(v1.x, 0.f); v1.y = fmaxf(v1.y, 0.f);
            *(float2*)(obase + (size_t)co * 4096 + px)       = v0;
            *(float2*)(obase + (size_t)(co + 8) * 4096 + px) = v1;
        }
    }
}

extern "C" void kernel_launch(void* const* d_in, const int* in_sizes, int n_in,
                              void* d_out, int out_size) {
    const float* u_t    = (const float*)d_in[0];
    const float* h_prev = (const float*)d_in[1];
    const int*   action = (const int*)d_in[2];
    const float* W_u    = (const float*)d_in[3];
    const float* W_h    = (const float*)d_in[4];
    float* out = (float*)d_out;

    cudaFuncSetAttribute(fernn_f16_kernel,
                         cudaFuncAttributeMaxDynamicSharedMemorySize, SMEM_TOTAL);

    prep_w_kernel<<<(18 * 16 * 8 * 8 * 4 + 255) / 256, 256>>>(W_h);
    prep_h_kernel<<<(int)(((size_t)144 * 64 * 64 * 64 + 255) / 256), 256>>>(h_prev);
    encoder_kernel<<<dim3(128, 16), 256>>>(u_t, W_u);
    fernn_f16_kernel<<<dim3(32, 9, 16), 256, SMEM_TOTAL>>>(action, out);
}

// round 14
// speedup vs baseline: 1.4229x; 1.3034x over previous
#include <cuda_runtime.h>
#include <cuda_fp16.h>
#include <cstdint>

// Problem constants
// u_t    [16,3,32,32]  f32   d_in[0]
// h_prev [16,9,128,64,64] f32 d_in[1]
// action [16,2] int32         d_in[2]
// W_u    [128,3,3,3] f32      d_in[3]
// W_h    [128,128,3,3] f32    d_in[4]
// out    [16,9,128,64,64] f32
#define WORLD 64
#define WIN   32
#define CC    128
#define VV    9

// ---- smem layout (per CTA, dynamic): two P planes only ----
// P plane: u64[16 slices][276]  (slice = ks*4+kq; row rc = ry*68+xx, ry 0..3, xx 0..65)
//   u64 = (half2 at ci-pair p = 8ks+kq, half2 at p+4); half2 = (ci=2p, ci=2p+1)
#define PD_BYTES (16*276*8)              // 35328
#define SMEM_TOTAL (2*PD_BYTES)          // 70656  (x2 CTAs = 138KB/SM)

// Scratch (device globals; no allocation allowed)
// g_Wg: [plane 18][sl 16][ct 8][lq 8] uint4 — per-thread A fragments (one LDG.128 each)
__device__ __align__(16) uint4 g_Wg[18 * 16 * 8 * 8];
__device__ __align__(16) uint32_t g_h16[144 * 64 * 64 * 64]; // [bv][ci-pair][y][x] half2
__device__ float g_uconv[16 * 128 * 32 * 32];                // [b][co][y][x]

// ---------------- helpers ----------------
__device__ __forceinline__ uint32_t smem_u32(const void* p) {
    uint32_t a;
    asm("{ .reg .u64 t; cvta.to.shared.u64 t, %1; cvt.u32.u64 %0, t; }" : "=r"(a) : "l"(p));
    return a;
}
__device__ __forceinline__ void lds64(uint32_t& lo, uint32_t& hi, uint32_t addr) {
    asm volatile("ld.shared.v2.b32 {%0,%1}, [%2];" : "=r"(lo), "=r"(hi) : "r"(addr));
}
__device__ __forceinline__ void mma_f16(float c[4], const uint4 a, const uint32_t b0, const uint32_t b1) {
    asm volatile(
        "mma.sync.aligned.m16n8k16.row.col.f32.f16.f16.f32 "
        "{%0,%1,%2,%3}, {%4,%5,%6,%7}, {%8,%9}, {%0,%1,%2,%3};"
        : "+f"(c[0]), "+f"(c[1]), "+f"(c[2]), "+f"(c[3])
        : "r"(a.x), "r"(a.y), "r"(a.z), "r"(a.w), "r"(b0), "r"(b1));
}
__device__ __forceinline__ void cpa4(uint32_t dst, const void* src) {
    asm volatile("cp.async.ca.shared.global [%0], [%1], 4;" :: "r"(dst), "l"(src));
}
__device__ __forceinline__ void cpa_commit() {
    asm volatile("cp.async.commit_group;" ::: "memory");
}
__device__ __forceinline__ void cpa_wait0() {
    asm volatile("cp.async.wait_group 0;" ::: "memory");
}

// ---------- prep: W_h -> per-thread fp16 A-fragment image ----------
// component idx = (((plane*16+sl)*8+ct)*8+lq)*4 + c
// c: co += (c&1)*8 ; ci += (c>>1)*8
__global__ void prep_w_kernel(const float* __restrict__ W_h) {
    int idx = blockIdx.x * blockDim.x + threadIdx.x;
    if (idx >= 18 * 16 * 8 * 8 * 4) return;
    int c     = idx & 3;
    int lq    = (idx >> 2) & 7;
    int ct    = (idx >> 5) & 7;
    int sl    = (idx >> 8) & 15;
    int plane = idx >> 12;            // 0..17 = chunk*9+tap
    int tap   = plane % 9;
    int chunk = plane / 9;
    int ks = sl >> 2, kq = sl & 3;
    int co = ct * 16 + lq + (c & 1) * 8;
    int ci = chunk * 64 + ks * 16 + 2 * kq + (c >> 1) * 8;
    float v0 = W_h[((size_t)co * 128 + ci) * 9 + tap];
    float v1 = W_h[((size_t)co * 128 + ci + 1) * 9 + tap];
    __half2 h = __floats2half2_rn(v0, v1);
    ((uint32_t*)g_Wg)[idx] = *(uint32_t*)&h;
}

// ---------- prep: h_prev -> half2 ci-pair planes (channel roll baked per (b,v)) ----------
__global__ void prep_h_kernel(const float* __restrict__ h_prev) {
    size_t idx = (size_t)blockIdx.x * 256 + threadIdx.x;
    if (idx >= (size_t)144 * 64 * 64 * 64) return;
    int xx = idx & 63;
    int gy = (idx >> 6) & 63;
    int p  = (idx >> 12) & 63;
    int bv = idx >> 18;                 // b*9+v
    int v  = bv % 9;
    int vy = v % 3 - 1;
    int c0 = (2 * p - vy + 128) & 127;
    int c1 = (2 * p + 1 - vy + 128) & 127;
    const float* hp = h_prev + (size_t)bv * CC * 4096;
    float f0 = hp[(size_t)c0 * 4096 + gy * 64 + xx];
    float f1 = hp[(size_t)c1 * 4096 + gy * 64 + xx];
    __half2 h = __floats2half2_rn(f0, f1);
    g_h16[idx] = *(uint32_t*)&h;
}

// ---------- encoder: circular conv u_t * W_u -> g_uconv (exact f32) ----------
__global__ void encoder_kernel(const float* __restrict__ u_t,
                               const float* __restrict__ W_u) {
    int co = blockIdx.x;
    int b  = blockIdx.y;
    __shared__ float us[3 * 32 * 32];
    __shared__ float ws[27];
    int tid = threadIdx.x;
    const float* up = u_t + (size_t)b * 3 * 1024;
    for (int e = tid; e < 3072; e += 256) us[e] = up[e];
    if (tid < 27) ws[tid] = W_u[co * 27 + tid];
    __syncthreads();

    int y  = (tid * 4) >> 5;
    int x0 = (tid * 4) & 31;
    float acc[4] = {0.f, 0.f, 0.f, 0.f};
#pragma unroll
    for (int ci = 0; ci < 3; ++ci)
#pragma unroll
        for (int ky = 0; ky < 3; ++ky) {
            int yy = (y + ky - 1 + 32) & 31;
#pragma unroll
            for (int kx = 0; kx < 3; ++kx) {
                float w = ws[ci * 9 + ky * 3 + kx];
#pragma unroll
                for (int k = 0; k < 4; ++k) {
                    int xx = (x0 + k + kx - 1 + 32) & 31;
                    acc[k] = fmaf(w, us[ci * 1024 + yy * 32 + xx], acc[k]);
                }
            }
        }
    float4 r = {acc[0], acc[1], acc[2], acc[3]};
    *(float4*)&g_uconv[((size_t)(b * 128 + co) * 32 + y) * 32 + x0] = r;
}

// ---------- main: fp16 m16n8k16; warp tile co64 x px64 (nt=8); 4 warps/CTA; 2 CTAs/SM ----------
// Block = (2-row tile, v, b); D[co=128][px=128]; warps: wco=wid&1, rl=wid>>1.
__global__ __launch_bounds__(128, 2)
void fernn_f16_kernel(const int* __restrict__ action,
                      float* __restrict__ out) {
    extern __shared__ unsigned char smem[];
    uint32_t sb = smem_u32(smem);

    int tid  = threadIdx.x;
    int wid  = tid >> 5;
    int lane = tid & 31;
    int wco = wid & 1;            // co half (64)
    int rl  = wid >> 1;           // output row in tile (0..1)
    int kq  = lane & 3;
    int lq  = lane >> 2;          // 0..7

    int y0 = blockIdx.x * 2;
    int v  = blockIdx.y;
    int b  = blockIdx.z;

    int ax = action[b * 2 + 0];
    int ay = action[b * 2 + 1];
    int vx = v / 3 - 1;
    // folded index (verified R2): in = h_prev[b,v,(ci-vy)%C,(y+ky-1+Sy)%H,(x+kx-1+Sx)%W]
    // channel roll baked into g_h16; here only spatial shifts:
    int Sy = ay - vx;
    int Sx = ax;
    const uint32_t* hbase = g_h16 + (size_t)(b * VV + v) * 64 * 4096;

    // ---- P-build mapping: 256 half-row units (p 0..31, ry 0..3, hf 0..1), 33 cols each ----
    int pgy_add = (y0 - 1 + Sy + 128);

    auto issueP = [&](int chunk) {
        uint32_t base = sb + (uint32_t)((chunk & 1) * PD_BYTES);
#pragma unroll
        for (int e0 = 0; e0 < 2; ++e0) {
            int e  = tid + e0 * 128;
            int p  = e >> 3;
            int ry = (e >> 1) & 3;
            int hf = e & 1;
            int ks = p >> 3, rem = p & 7;
            int kqp = rem & 3, phi = rem >> 2;
            uint32_t dst = base
                + (uint32_t)((((ks * 4 + kqp) * 276 + ry * 68) * 2 + phi) * 4)
                + (uint32_t)(hf * 33 * 8);
            int gy = (pgy_add + ry) & 63;
            int gx0 = hf * 33 - 1 + Sx + 64;
            const uint32_t* src = hbase + (size_t)(chunk * 32 + p) * 4096 + gy * 64;
#pragma unroll
            for (int j = 0; j < 33; ++j)
                cpa4(dst + j * 8, src + ((gx0 + j) & 63));
        }
    };

    float acc[4][8][4];
#pragma unroll
    for (int mt = 0; mt < 4; ++mt)
#pragma unroll
        for (int nt = 0; nt < 8; ++nt)
#pragma unroll
            for (int c = 0; c < 4; ++c) acc[mt][nt][c] = 0.f;

    // ---- prologue: P0 async; wait; then issue P1 (overlaps chunk-0 MMAs) ----
    issueP(0);
    cpa_commit();
    cpa_wait0();
    __syncthreads();
    issueP(1);
    cpa_commit();

#pragma unroll 1
    for (int chunk = 0; chunk < 2; ++chunk) {
        uint32_t pbuf = sb + (uint32_t)((chunk & 1) * PD_BYTES);

#pragma unroll 1
        for (int t = 0; t < 9; ++t) {
            int plane = chunk * 9 + t;
            int dy = t / 3;
            int dx = t % 3;
            // B row base: slice sl, row (rl+dy), column (px+dx), px = nt*8+lq
            uint32_t bb = pbuf + (uint32_t)(((rl + dy) * 68 + lq + dx) * 8);
            const uint4* wp = g_Wg + ((size_t)(plane * 16) * 8 + wco * 4) * 8 + lq;

#pragma unroll
            for (int ks = 0; ks < 4; ++ks) {
                int sl = ks * 4 + kq;
                uint4 A[4];
#pragma unroll
                for (int mt = 0; mt < 4; ++mt)
                    A[mt] = __ldg(wp + ((size_t)sl * 8 + mt) * 8);
                uint32_t bbs = bb + (uint32_t)((sl * 276) * 8);
#pragma unroll
                for (int nt = 0; nt < 8; ++nt) {
                    uint32_t B0, B1;
                    lds64(B0, B1, bbs + nt * 64);
#pragma unroll
                    for (int mt = 0; mt < 4; ++mt) mma_f16(acc[mt][nt], A[mt], B0, B1);
                }
            }
        }
        if (chunk == 0) {
            cpa_wait0();     // P1 resident
            __syncthreads();
        }
    }

    // ---- epilogue: +u (top-left window), relu, store ----
    int y = y0 + rl;
    float* obase = out + (size_t)((b * VV + v) * CC) * 4096 + (size_t)y * 64;
    bool rowu = (y < WIN);

#pragma unroll
    for (int mt = 0; mt < 4; ++mt) {
        int co = wco * 64 + mt * 16 + lq;
#pragma unroll
        for (int nt = 0; nt < 8; ++nt) {
            int px = nt * 8 + 2 * kq;
            float2 v0 = {acc[mt][nt][0], acc[mt][nt][1]};
            float2 v1 = {acc[mt][nt][2], acc[mt][nt][3]};
            if (rowu && px < WIN) {
                const float* u0 = g_uconv + (size_t)(b * CC + co) * 1024 + y * 32 + px;
                const float* u1 = g_uconv + (size_t)(b * CC + co + 8) * 1024 + y * 32 + px;
                v0.x += u0[0]; v0.y += u0[1];
                v1.x += u1[0]; v1.y += u1[1];
            }
            v0.x = fmaxf(v0.x, 0.f); v0.y = fmaxf(v0.y, 0.f);
            v1.x = fmaxf(v1.x, 0.f); v1.y = fmaxf(v1.y, 0.f);
            *(float2*)(obase + (size_t)co * 4096 + px)       = v0;
            *(float2*)(obase + (size_t)(co + 8) * 4096 + px) = v1;
        }
    }
}

extern "C" void kernel_launch(void* const* d_in, const int* in_sizes, int n_in,
                              void* d_out, int out_size) {
    const float* u_t    = (const float*)d_in[0];
    const float* h_prev = (const float*)d_in[1];
    const int*   action = (const int*)d_in[2];
    const float* W_u    = (const float*)d_in[3];
    const float* W_h    = (const float*)d_in[4];
    float* out = (float*)d_out;

    cudaFuncSetAttribute(fernn_f16_kernel,
                         cudaFuncAttributeMaxDynamicSharedMemorySize, SMEM_TOTAL);

    prep_w_kernel<<<(18 * 16 * 8 * 8 * 4 + 255) / 256, 256>>>(W_h);
    prep_h_kernel<<<(int)(((size_t)144 * 64 * 64 * 64 + 255) / 256), 256>>>(h_prev);
    encoder_kernel<<<dim3(128, 16), 256>>>(u_t, W_u);
    fernn_f16_kernel<<<dim3(32, 9, 16), 128, SMEM_TOTAL>>>(action, out);
}